// round 12
// baseline (speedup 1.0000x reference)
#include <cuda_runtime.h>
#include <cuda_fp16.h>
#include <cstdint>
#include <math.h>

// Problem constants (B=1, DIM=512, T=8, H=64, W=64)
#define MDIM 512
#define KDIM 512
#define NDIM 32768
#define SQRT_C 22.62741699796952f

// ---------------- main GEMM tiling (128x128, BK=32, fused convert+scale) ----------------
#define BM 128
#define BN 128
#define BK 32
#define NITER (KDIM / BK)      // 16
#define STAGES 3
#define AROW_H 40              // A padded row (halves) -> 80B
#define A_BYTES (BM * AROW_H * 2)        // 10240
#define B32_ROWB 528                     // fp32 B row: 128 floats + 4 pad = 528B
#define B32_BYTES (BK * B32_ROWB)        // 16896
#define STAGE_B (A_BYTES + B32_BYTES)    // 27136
#define BROW_H 136                       // fp16 B operand row (halves) -> 272B
#define BH16_OFF (STAGES * STAGE_B)      // 81408
#define BH16_BYTES (BK * BROW_H * 2)     // 8704
#define RED_OFF (BH16_OFF + BH16_BYTES)  // 90112 (256 float2 = 2048B)
#define SSM_OFF (RED_OFF + 2048)         // 92160 (128 floats = 512B)
#define SMEM_TOTAL (SSM_OFF + 512)       // 92672

// ---------------- fuse-weights GEMM tiling (R7 proven, BK=32) ----------------
#define FW_BK 32
#define FW_NITER 16
#define FW_AROW_H 40
#define FW_BROW_H 136
#define FW_A_BYTES (128 * FW_AROW_H * 2)     // 10240
#define FW_B_BYTES (32 * FW_BROW_H * 2)      // 8704
#define FW_STAGE_B (FW_A_BYTES + FW_B_BYTES) // 18944
#define FW_SMEM (5 * FW_STAGE_B)             // 94720

// ---------------- scratch ----------------
__device__ __half g_Wf[MDIM * KDIM];      // fused weight, fp16
__device__ __half g_wph[MDIM * KDIM];     // w_proj fp16
__device__ __half g_wvh[MDIM * KDIM];     // (W_v * gamma) fp16
__device__ float  g_bias[MDIM];

// ---------------- helpers ----------------
__device__ __forceinline__ uint32_t smem_u32(const void* p) {
    uint32_t a;
    asm("{ .reg .u64 t; cvta.to.shared.u64 t, %1; cvt.u32.u64 %0, t; }" : "=r"(a) : "l"(p));
    return a;
}
__device__ __forceinline__ void cp_async16(uint32_t dst, const void* src) {
    asm volatile("cp.async.cg.shared.global [%0], [%1], 16;" :: "r"(dst), "l"(src) : "memory");
}
#define LDSM_X4(r0, r1, r2, r3, addr)                                         \
    asm volatile("ldmatrix.sync.aligned.m8n8.x4.shared.b16 {%0,%1,%2,%3}, [%4];" \
        : "=r"(r0), "=r"(r1), "=r"(r2), "=r"(r3) : "r"(addr))
#define LDSM_X4_T(r0, r1, r2, r3, addr)                                       \
    asm volatile("ldmatrix.sync.aligned.m8n8.x4.trans.shared.b16 {%0,%1,%2,%3}, [%4];" \
        : "=r"(r0), "=r"(r1), "=r"(r2), "=r"(r3) : "r"(addr))

__device__ __forceinline__ void mma_f16(float c[4], uint32_t a0, uint32_t a1, uint32_t a2, uint32_t a3,
                                        uint32_t b0, uint32_t b1) {
    asm volatile(
        "mma.sync.aligned.m16n8k16.row.col.f32.f16.f16.f32 "
        "{%0,%1,%2,%3}, {%4,%5,%6,%7}, {%8,%9}, {%0,%1,%2,%3};"
        : "+f"(c[0]), "+f"(c[1]), "+f"(c[2]), "+f"(c[3])
        : "r"(a0), "r"(a1), "r"(a2), "r"(a3), "r"(b0), "r"(b1));
}

// ---------------- kernel 1: prep (fp16 weight converts) ----------------
__global__ __launch_bounds__(256) void prep_kernel(
    const float* __restrict__ w_proj, const float* __restrict__ w_qkv,
    const float* __restrict__ gamma,
    __half* __restrict__ wph, __half* __restrict__ wvh)
{
    const int bx  = blockIdx.x;
    const int tid = threadIdx.x;
    if (bx < 256) {
        const int i = (bx * 256 + tid) * 4;
        float4 v = *reinterpret_cast<const float4*>(w_proj + i);
        *reinterpret_cast<__half2*>(wph + i)     = __floats2half2_rn(v.x, v.y);
        *reinterpret_cast<__half2*>(wph + i + 2) = __floats2half2_rn(v.z, v.w);
    } else {
        const float* in = w_qkv + (size_t)1024 * KDIM;
        const int i = ((bx - 256) * 256 + tid) * 4;
        const int c = i & (KDIM - 1);
        float4 g = *reinterpret_cast<const float4*>(gamma + c);
        float4 v = *reinterpret_cast<const float4*>(in + i);
        *reinterpret_cast<__half2*>(wvh + i)     = __floats2half2_rn(v.x * g.x, v.y * g.y);
        *reinterpret_cast<__half2*>(wvh + i + 2) = __floats2half2_rn(v.z * g.z, v.w * g.w);
    }
}

// ---------------- kernel 2: fuse-weights mma (blocks 0..15) + bias (16..79) ----------------
__global__ __launch_bounds__(256, 2) void fw_bias_kernel(
    const __half* __restrict__ Awp, const __half* __restrict__ Bwv,
    const float* __restrict__ w_proj, const float* __restrict__ b_qkv,
    const float* __restrict__ b_proj,
    __half* __restrict__ Wf, float* __restrict__ bias)
{
    extern __shared__ char smem[];
    const int tid = threadIdx.x;

    if (blockIdx.x >= 16) {
        // ---- fused bias: warp per output row ----
        const int lane = tid & 31;
        const int o    = (blockIdx.x - 16) * 8 + (tid >> 5);
        const float* wp = w_proj + (size_t)o * KDIM;
        const float* bq = b_qkv + 1024;
        float acc = 0.f;
        #pragma unroll
        for (int i = 0; i < 16; i++) {
            const int k = lane + 32 * i;
            acc = fmaf(wp[k], bq[k], acc);
        }
        #pragma unroll
        for (int off = 16; off > 0; off >>= 1)
            acc += __shfl_xor_sync(0xFFFFFFFFu, acc, off);
        if (lane == 0) bias[o] = acc + b_proj[o];
        return;
    }

    // ---- fuse-weights GEMM: Wf = wph @ wvh  (B stride 512, 128x128 tiles) ----
    const uint32_t sbase = smem_u32(smem);
    const int bxx  = blockIdx.x;
    const int lane = tid & 31;
    const int wid  = tid >> 5;
    const int wm   = wid >> 2;
    const int wn   = wid & 3;
    const int ty   = lane >> 2;
    const int tx   = lane & 3;
    const int m0   = (bxx >> 2) * 128;
    const int n0   = (bxx & 3) * 128;

    const int a_row = tid >> 1;
    const int a_sp  = (tid & 1) * 2;
    const int b_row = tid >> 3;
    const int b_sp  = (tid & 7) * 2;
    const __half* a_src = Awp + (size_t)(m0 + a_row) * KDIM + a_sp * 8;
    const __half* b_src = Bwv + (size_t)b_row * 512 + n0 + b_sp * 8;

    float c[4][4][4] = {};

    auto issue = [&](int ck) {
        const uint32_t ab = sbase + (uint32_t)(ck % 5) * FW_STAGE_B;
        const uint32_t bb = ab + FW_A_BYTES;
        const int k0 = ck * FW_BK;
        #pragma unroll
        for (int ss = 0; ss < 2; ss++)
            cp_async16(ab + (uint32_t)(a_row * 80 + (a_sp + ss) * 16), a_src + k0 + ss * 8);
        #pragma unroll
        for (int ss = 0; ss < 2; ss++)
            cp_async16(bb + (uint32_t)(b_row * 272 + (b_sp + ss) * 16),
                       b_src + (size_t)k0 * 512 + ss * 8);
        asm volatile("cp.async.commit_group;" ::: "memory");
    };

    issue(0); issue(1); issue(2); issue(3);

    const uint32_t a_lm = (uint32_t)(((wm * 64 + (lane & 15)) * FW_AROW_H + (lane >> 4) * 8) * 2);
    const uint32_t b_lm = (uint32_t)(FW_A_BYTES + (((lane & 15)) * FW_BROW_H + wn * 32 + (lane >> 4) * 8) * 2);

    #pragma unroll 1
    for (int it = 0; it < FW_NITER; ++it) {
        if (it + 3 < FW_NITER)      asm volatile("cp.async.wait_group 3;" ::: "memory");
        else if (it + 2 < FW_NITER) asm volatile("cp.async.wait_group 2;" ::: "memory");
        else if (it + 1 < FW_NITER) asm volatile("cp.async.wait_group 1;" ::: "memory");
        else                        asm volatile("cp.async.wait_group 0;" ::: "memory");
        __syncthreads();
        if (it + 4 < FW_NITER) issue(it + 4);

        const uint32_t stb = sbase + (uint32_t)(it % 5) * FW_STAGE_B;
        #pragma unroll
        for (int kk = 0; kk < 2; kk++) {
            uint32_t a[4][4];
            #pragma unroll
            for (int mt = 0; mt < 4; mt++)
                LDSM_X4(a[mt][0], a[mt][1], a[mt][2], a[mt][3],
                        stb + a_lm + mt * (16 * FW_AROW_H * 2) + kk * 32);
            uint32_t b[4][2];
            #pragma unroll
            for (int ntp = 0; ntp < 2; ntp++)
                LDSM_X4_T(b[ntp * 2][0], b[ntp * 2][1], b[ntp * 2 + 1][0], b[ntp * 2 + 1][1],
                          stb + b_lm + kk * (16 * FW_BROW_H * 2) + ntp * 32);
            #pragma unroll
            for (int mt = 0; mt < 4; mt++)
                #pragma unroll
                for (int nt = 0; nt < 4; nt++)
                    mma_f16(c[mt][nt], a[mt][0], a[mt][1], a[mt][2], a[mt][3],
                            b[nt][0], b[nt][1]);
        }
    }

    #pragma unroll
    for (int mt = 0; mt < 4; mt++)
        #pragma unroll
        for (int h = 0; h < 2; h++) {
            const int m = m0 + wm * 64 + mt * 16 + ty + h * 8;
            #pragma unroll
            for (int nt = 0; nt < 4; nt++) {
                const int nc = wn * 32 + nt * 8 + 2 * tx;
                *reinterpret_cast<__half2*>(Wf + (size_t)m * KDIM + n0 + nc) =
                    __floats2half2_rn(c[mt][nt][h * 2 + 0], c[mt][nt][h * 2 + 1]);
            }
        }
}

// ================= kernel 3: main GEMM with fused f32->f16 convert + RMS scale =================
// B tiles arrive as fp32 x via cp.async; converted in-register to a single fp16
// operand buffer while accumulating per-token sum(x^2). s[n] finalized in smem
// before the epilogue. No xh buffer, no separate scale pass.
__global__ __launch_bounds__(256, 2) void main_gemm_kernel(
    const __half* __restrict__ A,    // Wf [512,512] fp16
    const float* __restrict__ X,     // x  [512,32768] fp32
    const float* __restrict__ bias,
    float* __restrict__ C)
{
    extern __shared__ char smem[];
    const uint32_t sbase = smem_u32(smem);
    const int tid  = threadIdx.x;
    const int lane = tid & 31;
    const int wid  = tid >> 5;
    const int wm   = wid >> 2;          // 0..1
    const int wn   = wid & 3;           // 0..3
    const int ty   = lane >> 2;
    const int tx   = lane & 3;
    const int m0   = blockIdx.x * BM;   // 4 m-tiles, fastest (L2 reuse of x)
    const int n0   = blockIdx.y * BN;   // 256 n-tiles

    // A loader: 512 segs of 16B, 2/thread
    const int a_row = tid >> 1;
    const int a_sp  = (tid & 1) * 2;
    const __half* a_src = A + (size_t)(m0 + a_row) * KDIM + a_sp * 8;
    // B fp32 loader: 32 rows x 512B = 1024 segs, 4/thread
    const int b_kr = tid >> 3;
    const int b_sg = tid & 7;
    const float* b_src = X + (size_t)b_kr * NDIM + n0 + b_sg * 4;

    // converter mapping: token pair p (n = 2p, 2p+1), k-slice h (8 k each)
    const int cp_ = tid & 63;
    const int ch  = tid >> 6;

    float c[4][4][4] = {};
    float ssx = 0.f, ssy = 0.f;

    auto issue = [&](int ck) {
        const uint32_t ab = sbase + (uint32_t)(ck % STAGES) * STAGE_B;
        const uint32_t bb = ab + A_BYTES;
        const int k0 = ck * BK;
        #pragma unroll
        for (int ss = 0; ss < 2; ss++)
            cp_async16(ab + (uint32_t)(a_row * 80 + (a_sp + ss) * 16), a_src + k0 + ss * 8);
        #pragma unroll
        for (int j = 0; j < 4; j++)
            cp_async16(bb + (uint32_t)(b_kr * B32_ROWB + (b_sg + 8 * j) * 16),
                       b_src + (size_t)k0 * NDIM + 8 * j * 4);
        asm volatile("cp.async.commit_group;" ::: "memory");
    };

    issue(0); issue(1);

    const uint32_t a_lm = (uint32_t)(((wm * 64 + (lane & 15)) * AROW_H + (lane >> 4) * 8) * 2);
    const uint32_t b_lm = (uint32_t)(BH16_OFF + (((lane & 15)) * BROW_H + wn * 32 + (lane >> 4) * 8) * 2);

    #pragma unroll 1
    for (int it = 0; it < NITER; ++it) {
        if (it + 1 < NITER) asm volatile("cp.async.wait_group 1;" ::: "memory");
        else                asm volatile("cp.async.wait_group 0;" ::: "memory");
        __syncthreads();     // stage `it` arrived; everyone done with fp16 buf of it-1
        if (it + 2 < NITER) issue(it + 2);

        // ---- convert fp32 stage -> fp16 operand buffer, accumulate ssq ----
        {
            const char* b32 = smem + (uint32_t)(it % STAGES) * STAGE_B + A_BYTES;
            #pragma unroll
            for (int i = 0; i < 8; i++) {
                const int k = ch * 8 + i;
                float2 v = *reinterpret_cast<const float2*>(b32 + k * B32_ROWB + cp_ * 8);
                ssx = fmaf(v.x, v.x, ssx);
                ssy = fmaf(v.y, v.y, ssy);
                *reinterpret_cast<__half2*>(smem + BH16_OFF + k * 272 + cp_ * 4) =
                    __floats2half2_rn(v.x, v.y);
            }
        }
        __syncthreads();     // fp16 operand visible to all warps

        // ---- compute ----
        #pragma unroll
        for (int kk = 0; kk < 2; kk++) {
            uint32_t a[4][4];
            #pragma unroll
            for (int mt = 0; mt < 4; mt++)
                LDSM_X4(a[mt][0], a[mt][1], a[mt][2], a[mt][3],
                        sbase + (uint32_t)(it % STAGES) * STAGE_B + a_lm
                        + mt * (16 * AROW_H * 2) + kk * 32);
            uint32_t b[4][2];
            #pragma unroll
            for (int ntp = 0; ntp < 2; ntp++)
                LDSM_X4_T(b[ntp * 2][0], b[ntp * 2][1], b[ntp * 2 + 1][0], b[ntp * 2 + 1][1],
                          sbase + b_lm + kk * (16 * BROW_H * 2) + ntp * 32);
            #pragma unroll
            for (int mt = 0; mt < 4; mt++)
                #pragma unroll
                for (int nt = 0; nt < 4; nt++)
                    mma_f16(c[mt][nt], a[mt][0], a[mt][1], a[mt][2], a[mt][3],
                            b[nt][0], b[nt][1]);
        }
    }

    // ---- finalize per-token scale s[n] in smem ----
    {
        float2* red = reinterpret_cast<float2*>(smem + RED_OFF);
        red[tid] = make_float2(ssx, ssy);
        __syncthreads();
        if (tid < 64) {
            float2 a = red[tid], b = red[tid + 64], c2 = red[tid + 128], d = red[tid + 192];
            float sx = a.x + b.x + c2.x + d.x;
            float sy = a.y + b.y + c2.y + d.y;
            float2 sv;
            sv.x = SQRT_C / fmaxf(sqrtf(sx), 1e-12f);
            sv.y = SQRT_C / fmaxf(sqrtf(sy), 1e-12f);
            *reinterpret_cast<float2*>(smem + SSM_OFF + tid * 8) = sv;
        }
        __syncthreads();
    }

    // ---- epilogue: out = D*s[n] + bias[m] + x[m][n] (fp32 residual via L2) ----
    const float* s_sm = reinterpret_cast<const float*>(smem + SSM_OFF);
    #pragma unroll
    for (int mt = 0; mt < 4; mt++) {
        #pragma unroll
        for (int h = 0; h < 2; h++) {
            const int m = m0 + wm * 64 + mt * 16 + ty + h * 8;
            const float bm = bias[m];
            const float* xrow = X + (size_t)m * NDIM + n0;
            float* crow = C + (size_t)m * NDIM + n0;
            #pragma unroll
            for (int nt = 0; nt < 4; nt++) {
                const int nc = wn * 32 + nt * 8 + 2 * tx;
                float2 xv = *reinterpret_cast<const float2*>(xrow + nc);
                float2 sv = *reinterpret_cast<const float2*>(s_sm + nc);
                float2 ov;
                ov.x = fmaf(c[mt][nt][h * 2 + 0], sv.x, bm + xv.x);
                ov.y = fmaf(c[mt][nt][h * 2 + 1], sv.y, bm + xv.y);
                *reinterpret_cast<float2*>(crow + nc) = ov;
            }
        }
    }
}

// ---------------- launcher ----------------
extern "C" void kernel_launch(void* const* d_in, const int* in_sizes, int n_in,
                              void* d_out, int out_size)
{
    const float* x      = (const float*)d_in[0];
    const float* gamma  = (const float*)d_in[1];
    const float* w_qkv  = (const float*)d_in[2];
    const float* b_qkv  = (const float*)d_in[3];
    const float* w_proj = (const float*)d_in[4];
    const float* b_proj = (const float*)d_in[5];
    float* out = (float*)d_out;

    __half *Wf, *wph, *wvh;
    float *bias;
    cudaGetSymbolAddress((void**)&Wf,   g_Wf);
    cudaGetSymbolAddress((void**)&wph,  g_wph);
    cudaGetSymbolAddress((void**)&wvh,  g_wvh);
    cudaGetSymbolAddress((void**)&bias, g_bias);

    cudaFuncSetAttribute(fw_bias_kernel,
                         cudaFuncAttributeMaxDynamicSharedMemorySize, FW_SMEM);
    cudaFuncSetAttribute(main_gemm_kernel,
                         cudaFuncAttributeMaxDynamicSharedMemorySize, SMEM_TOTAL);

    prep_kernel<<<512, 256>>>(w_proj, w_qkv, gamma, wph, wvh);
    fw_bias_kernel<<<80, 256, FW_SMEM>>>(wph, wvh, w_proj, b_qkv, b_proj, Wf, bias);

    dim3 grid(MDIM / BM, NDIM / BN);   // (4, 256): m fastest
    main_gemm_kernel<<<grid, 256, SMEM_TOTAL>>>(Wf, x, bias, out);
}

// round 13
// speedup vs baseline: 1.1486x; 1.1486x over previous
#include <cuda_runtime.h>
#include <cuda_fp16.h>
#include <cstdint>
#include <math.h>

// Problem constants (B=1, DIM=512, T=8, H=64, W=64)
#define MDIM 512
#define KDIM 512
#define NDIM 32768
#define SQRT_C 22.62741699796952f

// ---------------- GEMM tiling (shared: main + fw), R7-proven ----------------
#define BM 128
#define BN 128
#define BK 32
#define NITER (KDIM / BK)      // 16
#define STAGES 5
#define AROW_H 40              // A padded row (halves) -> 80B
#define BROW_H 136             // B padded row (halves) -> 272B
#define A_BYTES (BM * AROW_H * 2)      // 10240
#define B_BYTES (BK * BROW_H * 2)      // 8704
#define STAGE_B (A_BYTES + B_BYTES)    // 18944
#define SMEM_TOTAL (STAGES * STAGE_B)  // 94720

// ---------------- scratch ----------------
__device__ __half g_Wf[MDIM * KDIM];      // fused weight, fp16
__device__ __half g_xh[KDIM * NDIM];      // x converted to fp16
__device__ __half g_wph[MDIM * KDIM];     // w_proj fp16
__device__ __half g_wvh[MDIM * KDIM];     // (W_v * gamma) fp16
__device__ float  g_bias[MDIM];
__device__ float  g_s[NDIM];

// ---------------- helpers ----------------
__device__ __forceinline__ uint32_t smem_u32(const void* p) {
    uint32_t a;
    asm("{ .reg .u64 t; cvta.to.shared.u64 t, %1; cvt.u32.u64 %0, t; }" : "=r"(a) : "l"(p));
    return a;
}
__device__ __forceinline__ void cp_async16(uint32_t dst, const void* src) {
    asm volatile("cp.async.cg.shared.global [%0], [%1], 16;" :: "r"(dst), "l"(src) : "memory");
}
#define LDSM_X4(r0, r1, r2, r3, addr)                                         \
    asm volatile("ldmatrix.sync.aligned.m8n8.x4.shared.b16 {%0,%1,%2,%3}, [%4];" \
        : "=r"(r0), "=r"(r1), "=r"(r2), "=r"(r3) : "r"(addr))
#define LDSM_X4_T(r0, r1, r2, r3, addr)                                       \
    asm volatile("ldmatrix.sync.aligned.m8n8.x4.trans.shared.b16 {%0,%1,%2,%3}, [%4];" \
        : "=r"(r0), "=r"(r1), "=r"(r2), "=r"(r3) : "r"(addr))

__device__ __forceinline__ void mma_f16(float c[4], uint32_t a0, uint32_t a1, uint32_t a2, uint32_t a3,
                                        uint32_t b0, uint32_t b1) {
    asm volatile(
        "mma.sync.aligned.m16n8k16.row.col.f32.f16.f16.f32 "
        "{%0,%1,%2,%3}, {%4,%5,%6,%7}, {%8,%9}, {%0,%1,%2,%3};"
        : "+f"(c[0]), "+f"(c[1]), "+f"(c[2]), "+f"(c[3])
        : "r"(a0), "r"(a1), "r"(a2), "r"(a3), "r"(b0), "r"(b1));
}

// ================= kernel 1: streaming prep (low regs, tiny smem) =================
// blocks 0..511    : RMS scale + fp16 conversion of x (64 tokens/block)
// blocks 512..767  : w_proj -> fp16
// blocks 768..1023 : (W_v * gamma) -> fp16
// blocks 1024..1087: fused bias (warp per output row)
__global__ __launch_bounds__(256) void stream_prep_kernel(
    const float* __restrict__ x,
    const float* __restrict__ gamma,
    const float* __restrict__ w_qkv,
    const float* __restrict__ b_qkv,
    const float* __restrict__ w_proj,
    const float* __restrict__ b_proj,
    __half* __restrict__ wph, __half* __restrict__ wvh,
    float* __restrict__ bias,
    float* __restrict__ s, __half* __restrict__ xh)
{
    __shared__ float2 red[256];
    const int bx  = blockIdx.x;
    const int tid = threadIdx.x;

    if (bx < 512) {
        // ---- RMS scale + fp16 convert: 64 tokens, 32 pairs x 8 k-groups ----
        const int pair = tid & 31;
        const int kg   = tid >> 5;          // 0..7, 64 k each
        const int n    = bx * 64 + pair * 2;

        const float2* p = reinterpret_cast<const float2*>(x + (size_t)(kg * 64) * NDIM + n);
        __half2* ph = reinterpret_cast<__half2*>(xh + (size_t)(kg * 64) * NDIM + n);
        float ax = 0.f, ay = 0.f;
        #pragma unroll 8
        for (int c = 0; c < 64; c++) {
            float2 v = p[(size_t)c * (NDIM / 2)];
            ax = fmaf(v.x, v.x, ax);
            ay = fmaf(v.y, v.y, ay);
            ph[(size_t)c * (NDIM / 2)] = __floats2half2_rn(v.x, v.y);
        }
        red[tid] = make_float2(ax, ay);
        __syncthreads();
        if (tid < 32) {
            float sx = 0.f, sy = 0.f;
            #pragma unroll
            for (int j = 0; j < 8; j++) {
                float2 v = red[tid + 32 * j];
                sx += v.x; sy += v.y;
            }
            float2 sv;
            sv.x = SQRT_C / fmaxf(sqrtf(sx), 1e-12f);
            sv.y = SQRT_C / fmaxf(sqrtf(sy), 1e-12f);
            *reinterpret_cast<float2*>(s + bx * 64 + tid * 2) = sv;
        }
        return;
    }

    if (bx < 768) {
        // ---- w_proj -> fp16 ----
        const int i = ((bx - 512) * 256 + tid) * 4;
        float4 v = *reinterpret_cast<const float4*>(w_proj + i);
        *reinterpret_cast<__half2*>(wph + i)     = __floats2half2_rn(v.x, v.y);
        *reinterpret_cast<__half2*>(wph + i + 2) = __floats2half2_rn(v.z, v.w);
        return;
    }

    if (bx < 1024) {
        // ---- (W_v * gamma) -> fp16 ----
        const float* in = w_qkv + (size_t)1024 * KDIM;
        const int i = ((bx - 768) * 256 + tid) * 4;
        const int c = i & (KDIM - 1);
        float4 g = *reinterpret_cast<const float4*>(gamma + c);
        float4 v = *reinterpret_cast<const float4*>(in + i);
        *reinterpret_cast<__half2*>(wvh + i)     = __floats2half2_rn(v.x * g.x, v.y * g.y);
        *reinterpret_cast<__half2*>(wvh + i + 2) = __floats2half2_rn(v.z * g.z, v.w * g.w);
        return;
    }

    // ---- fused bias: warp per output row ----
    {
        const int lane = tid & 31;
        const int o    = (bx - 1024) * 8 + (tid >> 5);
        const float* wp = w_proj + (size_t)o * KDIM;
        const float* bq = b_qkv + 1024;
        float acc = 0.f;
        #pragma unroll
        for (int i = 0; i < 16; i++) {
            const int k = lane + 32 * i;
            acc = fmaf(wp[k], bq[k], acc);
        }
        #pragma unroll
        for (int off = 16; off > 0; off >>= 1)
            acc += __shfl_xor_sync(0xFFFFFFFFu, acc, off);
        if (lane == 0) bias[o] = acc + b_proj[o];
    }
}

// ================= kernel 2: fuse-weights GEMM only (16 blocks) =================
__global__ __launch_bounds__(256, 2) void fw_kernel(
    const __half* __restrict__ Awp, const __half* __restrict__ Bwv,
    __half* __restrict__ Wf)
{
    extern __shared__ char smem[];
    const uint32_t sbase = smem_u32(smem);
    const int tid  = threadIdx.x;
    const int lane = tid & 31;
    const int wid  = tid >> 5;
    const int wm   = wid >> 2;
    const int wn   = wid & 3;
    const int ty   = lane >> 2;
    const int tx   = lane & 3;
    const int m0   = (blockIdx.x >> 2) * BM;
    const int n0   = (blockIdx.x & 3) * BN;

    const int a_row = tid >> 1;
    const int a_sp  = (tid & 1) * 2;
    const int b_row = tid >> 3;
    const int b_sp  = (tid & 7) * 2;
    const __half* a_src = Awp + (size_t)(m0 + a_row) * KDIM + a_sp * 8;
    const __half* b_src = Bwv + (size_t)b_row * 512 + n0 + b_sp * 8;

    float c[4][4][4] = {};

    auto issue = [&](int ck) {
        const uint32_t ab = sbase + (uint32_t)(ck % STAGES) * STAGE_B;
        const uint32_t bb = ab + A_BYTES;
        const int k0 = ck * BK;
        #pragma unroll
        for (int ss = 0; ss < 2; ss++)
            cp_async16(ab + (uint32_t)(a_row * 80 + (a_sp + ss) * 16), a_src + k0 + ss * 8);
        #pragma unroll
        for (int ss = 0; ss < 2; ss++)
            cp_async16(bb + (uint32_t)(b_row * 272 + (b_sp + ss) * 16),
                       b_src + (size_t)k0 * 512 + ss * 8);
        asm volatile("cp.async.commit_group;" ::: "memory");
    };

    issue(0); issue(1); issue(2); issue(3);

    const uint32_t a_lm = (uint32_t)(((wm * 64 + (lane & 15)) * AROW_H + (lane >> 4) * 8) * 2);
    const uint32_t b_lm = (uint32_t)(A_BYTES + (((lane & 15)) * BROW_H + wn * 32 + (lane >> 4) * 8) * 2);

    #pragma unroll 1
    for (int it = 0; it < NITER; ++it) {
        if (it + 3 < NITER)      asm volatile("cp.async.wait_group 3;" ::: "memory");
        else if (it + 2 < NITER) asm volatile("cp.async.wait_group 2;" ::: "memory");
        else if (it + 1 < NITER) asm volatile("cp.async.wait_group 1;" ::: "memory");
        else                     asm volatile("cp.async.wait_group 0;" ::: "memory");
        __syncthreads();
        if (it + 4 < NITER) issue(it + 4);

        const uint32_t stb = sbase + (uint32_t)(it % STAGES) * STAGE_B;
        #pragma unroll
        for (int kk = 0; kk < 2; kk++) {
            uint32_t a[4][4];
            #pragma unroll
            for (int mt = 0; mt < 4; mt++)
                LDSM_X4(a[mt][0], a[mt][1], a[mt][2], a[mt][3],
                        stb + a_lm + mt * (16 * AROW_H * 2) + kk * 32);
            uint32_t b[4][2];
            #pragma unroll
            for (int ntp = 0; ntp < 2; ntp++)
                LDSM_X4_T(b[ntp * 2][0], b[ntp * 2][1], b[ntp * 2 + 1][0], b[ntp * 2 + 1][1],
                          stb + b_lm + kk * (16 * BROW_H * 2) + ntp * 32);
            #pragma unroll
            for (int mt = 0; mt < 4; mt++)
                #pragma unroll
                for (int nt = 0; nt < 4; nt++)
                    mma_f16(c[mt][nt], a[mt][0], a[mt][1], a[mt][2], a[mt][3],
                            b[nt][0], b[nt][1]);
        }
    }

    #pragma unroll
    for (int mt = 0; mt < 4; mt++)
        #pragma unroll
        for (int h = 0; h < 2; h++) {
            const int m = m0 + wm * 64 + mt * 16 + ty + h * 8;
            #pragma unroll
            for (int nt = 0; nt < 4; nt++) {
                const int nc = wn * 32 + nt * 8 + 2 * tx;
                *reinterpret_cast<__half2*>(Wf + (size_t)m * KDIM + n0 + nc) =
                    __floats2half2_rn(c[mt][nt][h * 2 + 0], c[mt][nt][h * 2 + 1]);
            }
        }
}

// ================= kernel 3: main GEMM (R7-proven: 5-stage, per-kk LDSM) =================
__global__ __launch_bounds__(256, 2) void main_gemm_kernel(
    const __half* __restrict__ A,    // Wf [512,512] fp16
    const __half* __restrict__ Bh,   // x_h [512,32768] fp16 (operand + residual)
    const float* __restrict__ s,
    const float* __restrict__ bias,
    float* __restrict__ C)
{
    extern __shared__ char smem[];
    const uint32_t sbase = smem_u32(smem);
    const int tid  = threadIdx.x;
    const int lane = tid & 31;
    const int wid  = tid >> 5;
    const int wm   = wid >> 2;
    const int wn   = wid & 3;
    const int ty   = lane >> 2;
    const int tx   = lane & 3;
    const int m0   = blockIdx.x * BM;   // 4 m-tiles fastest (L2 reuse of xh)
    const int n0   = blockIdx.y * BN;   // 256 n-tiles

    const int a_row = tid >> 1;
    const int a_sp  = (tid & 1) * 2;
    const int b_row = tid >> 3;
    const int b_sp  = (tid & 7) * 2;
    const __half* a_src = A + (size_t)(m0 + a_row) * KDIM + a_sp * 8;
    const __half* b_src = Bh + (size_t)b_row * NDIM + n0 + b_sp * 8;

    float c[4][4][4] = {};

    auto issue = [&](int ck) {
        const uint32_t ab = sbase + (uint32_t)(ck % STAGES) * STAGE_B;
        const uint32_t bb = ab + A_BYTES;
        const int k0 = ck * BK;
        #pragma unroll
        for (int ss = 0; ss < 2; ss++)
            cp_async16(ab + (uint32_t)(a_row * 80 + (a_sp + ss) * 16), a_src + k0 + ss * 8);
        #pragma unroll
        for (int ss = 0; ss < 2; ss++)
            cp_async16(bb + (uint32_t)(b_row * 272 + (b_sp + ss) * 16),
                       b_src + (size_t)k0 * NDIM + ss * 8);
        asm volatile("cp.async.commit_group;" ::: "memory");
    };

    issue(0); issue(1); issue(2); issue(3);

    const uint32_t a_lm = (uint32_t)(((wm * 64 + (lane & 15)) * AROW_H + (lane >> 4) * 8) * 2);
    const uint32_t b_lm = (uint32_t)(A_BYTES + (((lane & 15)) * BROW_H + wn * 32 + (lane >> 4) * 8) * 2);

    #pragma unroll 1
    for (int it = 0; it < NITER; ++it) {
        if (it + 3 < NITER)      asm volatile("cp.async.wait_group 3;" ::: "memory");
        else if (it + 2 < NITER) asm volatile("cp.async.wait_group 2;" ::: "memory");
        else if (it + 1 < NITER) asm volatile("cp.async.wait_group 1;" ::: "memory");
        else                     asm volatile("cp.async.wait_group 0;" ::: "memory");
        __syncthreads();
        if (it + 4 < NITER) issue(it + 4);

        const uint32_t stb = sbase + (uint32_t)(it % STAGES) * STAGE_B;
        #pragma unroll
        for (int kk = 0; kk < 2; kk++) {
            uint32_t a[4][4];
            #pragma unroll
            for (int mt = 0; mt < 4; mt++)
                LDSM_X4(a[mt][0], a[mt][1], a[mt][2], a[mt][3],
                        stb + a_lm + mt * (16 * AROW_H * 2) + kk * 32);
            uint32_t b[4][2];
            #pragma unroll
            for (int ntp = 0; ntp < 2; ntp++)
                LDSM_X4_T(b[ntp * 2][0], b[ntp * 2][1], b[ntp * 2 + 1][0], b[ntp * 2 + 1][1],
                          stb + b_lm + kk * (16 * BROW_H * 2) + ntp * 32);
            #pragma unroll
            for (int mt = 0; mt < 4; mt++)
                #pragma unroll
                for (int nt = 0; nt < 4; nt++)
                    mma_f16(c[mt][nt], a[mt][0], a[mt][1], a[mt][2], a[mt][3],
                            b[nt][0], b[nt][1]);
        }
    }

    // ---- epilogue: out = D*s[n] + bias[m] + xh[m][n] ----
    #pragma unroll
    for (int mt = 0; mt < 4; mt++) {
        #pragma unroll
        for (int h = 0; h < 2; h++) {
            const int m = m0 + wm * 64 + mt * 16 + ty + h * 8;
            const float bm = bias[m];
            const __half2* xrow = reinterpret_cast<const __half2*>(Bh + (size_t)m * NDIM + n0);
            float* crow = C + (size_t)m * NDIM + n0;
            #pragma unroll
            for (int nt = 0; nt < 4; nt++) {
                const int nc = wn * 32 + nt * 8 + 2 * tx;
                float2 xv = __half22float2(xrow[nc >> 1]);
                float2 sv = *reinterpret_cast<const float2*>(s + n0 + nc);
                float2 ov;
                ov.x = fmaf(c[mt][nt][h * 2 + 0], sv.x, bm + xv.x);
                ov.y = fmaf(c[mt][nt][h * 2 + 1], sv.y, bm + xv.y);
                *reinterpret_cast<float2*>(crow + nc) = ov;
            }
        }
    }
}

// ---------------- launcher ----------------
extern "C" void kernel_launch(void* const* d_in, const int* in_sizes, int n_in,
                              void* d_out, int out_size)
{
    const float* x      = (const float*)d_in[0];
    const float* gamma  = (const float*)d_in[1];
    const float* w_qkv  = (const float*)d_in[2];
    const float* b_qkv  = (const float*)d_in[3];
    const float* w_proj = (const float*)d_in[4];
    const float* b_proj = (const float*)d_in[5];
    float* out = (float*)d_out;

    __half *Wf, *xh, *wph, *wvh;
    float *bias, *s;
    cudaGetSymbolAddress((void**)&Wf,   g_Wf);
    cudaGetSymbolAddress((void**)&xh,   g_xh);
    cudaGetSymbolAddress((void**)&wph,  g_wph);
    cudaGetSymbolAddress((void**)&wvh,  g_wvh);
    cudaGetSymbolAddress((void**)&bias, g_bias);
    cudaGetSymbolAddress((void**)&s,    g_s);

    cudaFuncSetAttribute(fw_kernel,
                         cudaFuncAttributeMaxDynamicSharedMemorySize, SMEM_TOTAL);
    cudaFuncSetAttribute(main_gemm_kernel,
                         cudaFuncAttributeMaxDynamicSharedMemorySize, SMEM_TOTAL);

    // kernel1: scale(512) + wph(256) + wvh(256) + bias(64) = 1088 blocks, low regs/smem
    stream_prep_kernel<<<1088, 256>>>(x, gamma, w_qkv, b_qkv, w_proj, b_proj,
                                      wph, wvh, bias, s, xh);
    // kernel2: fuse-weights GEMM (needs wph/wvh)
    fw_kernel<<<16, 256, SMEM_TOTAL>>>(wph, wvh, Wf);
    // kernel3: main GEMM
    dim3 grid(MDIM / BM, NDIM / BN);   // (4, 256): m fastest
    main_gemm_kernel<<<grid, 256, SMEM_TOTAL>>>(Wf, xh, s, bias, out);
}

// round 14
// speedup vs baseline: 1.1874x; 1.0337x over previous
#include <cuda_runtime.h>
#include <cuda_fp16.h>
#include <cstdint>
#include <math.h>

// Problem constants (B=1, DIM=512, T=8, H=64, W=64)
#define MDIM 512
#define KDIM 512
#define NDIM 32768
#define SQRT_C 22.62741699796952f

// ---------------- main GEMM tiling (R7-proven) ----------------
#define BM 128
#define BN 128
#define BK 32
#define NITER (KDIM / BK)      // 16
#define STAGES 5
#define AROW_H 40              // A padded row (halves) -> 80B
#define BROW_H 136             // B padded row (halves) -> 272B
#define A_BYTES (BM * AROW_H * 2)      // 10240
#define B_BYTES (BK * BROW_H * 2)      // 8704
#define STAGE_B (A_BYTES + B_BYTES)    // 18944
#define SMEM_TOTAL (STAGES * STAGE_B)  // 94720

// ---------------- aux kernel: fw 64x128 single-stage ----------------
#define FWA_BYTES (64 * 80)            // 5120
#define FWB_BYTES (32 * 272)           // 8704
#define AUX_SMEM (FWA_BYTES + FWB_BYTES)  // 13824

// ---------------- scratch ----------------
__device__ __half g_Wf[MDIM * KDIM];      // fused weight, fp16
__device__ __half g_xh[KDIM * NDIM];      // x converted to fp16
__device__ float  g_bias[MDIM];
__device__ float  g_s[NDIM];

// ---------------- helpers ----------------
__device__ __forceinline__ uint32_t smem_u32(const void* p) {
    uint32_t a;
    asm("{ .reg .u64 t; cvta.to.shared.u64 t, %1; cvt.u32.u64 %0, t; }" : "=r"(a) : "l"(p));
    return a;
}
__device__ __forceinline__ void cp_async16(uint32_t dst, const void* src) {
    asm volatile("cp.async.cg.shared.global [%0], [%1], 16;" :: "r"(dst), "l"(src) : "memory");
}
#define LDSM_X4(r0, r1, r2, r3, addr)                                         \
    asm volatile("ldmatrix.sync.aligned.m8n8.x4.shared.b16 {%0,%1,%2,%3}, [%4];" \
        : "=r"(r0), "=r"(r1), "=r"(r2), "=r"(r3) : "r"(addr))
#define LDSM_X4_T(r0, r1, r2, r3, addr)                                       \
    asm volatile("ldmatrix.sync.aligned.m8n8.x4.trans.shared.b16 {%0,%1,%2,%3}, [%4];" \
        : "=r"(r0), "=r"(r1), "=r"(r2), "=r"(r3) : "r"(addr))

__device__ __forceinline__ void mma_f16(float c[4], uint32_t a0, uint32_t a1, uint32_t a2, uint32_t a3,
                                        uint32_t b0, uint32_t b1) {
    asm volatile(
        "mma.sync.aligned.m16n8k16.row.col.f32.f16.f16.f32 "
        "{%0,%1,%2,%3}, {%4,%5,%6,%7}, {%8,%9}, {%0,%1,%2,%3};"
        : "+f"(c[0]), "+f"(c[1]), "+f"(c[2]), "+f"(c[3])
        : "r"(a0), "r"(a1), "r"(a2), "r"(a3), "r"(b0), "r"(b1));
}
__device__ __forceinline__ void sts16_h8(uint32_t addr, const __half2 h[4]) {
    asm volatile("st.shared.v4.b32 [%0], {%1,%2,%3,%4};" :: "r"(addr),
        "r"(*(const uint32_t*)&h[0]), "r"(*(const uint32_t*)&h[1]),
        "r"(*(const uint32_t*)&h[2]), "r"(*(const uint32_t*)&h[3]) : "memory");
}

// ================= kernel 1 (aux): fw-GEMM(inline cvt) + bias + scale =================
// blocks 0..31   : fuse-weights GEMM, 64x128 tiles, inline fp32->fp16 conversion
// blocks 32..95  : fused bias (warp per output row)
// blocks 96..607 : RMS scale + fp16 conversion of x (64 tokens/block)
__global__ __launch_bounds__(256, 3) void aux_kernel(
    const float* __restrict__ x,
    const float* __restrict__ gamma,
    const float* __restrict__ w_qkv,
    const float* __restrict__ b_qkv,
    const float* __restrict__ w_proj,
    const float* __restrict__ b_proj,
    __half* __restrict__ Wf, float* __restrict__ bias,
    float* __restrict__ s, __half* __restrict__ xh)
{
    extern __shared__ char smem[];
    const int bx  = blockIdx.x;
    const int tid = threadIdx.x;

    if (bx < 32) {
        // ---- fuse-weights GEMM: Wf[m][c] = sum_k w_proj[m][k]*(Wv[k][c]*gamma[c]) ----
        const uint32_t sbase = smem_u32(smem);
        const int lane = tid & 31;
        const int wid  = tid >> 5;
        const int wm   = wid >> 2;          // 0..1 (32-row halves)
        const int wn   = wid & 3;           // 0..3
        const int ty   = lane >> 2;
        const int tx   = lane & 3;
        const int m0   = (bx >> 2) * 64;
        const int n0   = (bx & 3) * 128;

        // A staging: 64 rows x 32 k fp32 -> fp16 [64][40h]
        const int a_row = tid >> 2;         // 0..63
        const int a_ks  = (tid & 3) * 8;    // k offset (floats)
        // B staging: 32 k-rows x 128 c fp32 -> fp16 [32][136h]
        const int b_kr  = tid >> 3;         // 0..31
        const int b_cs  = (tid & 7) * 16;   // c offset (floats)

        const float* wv = w_qkv + (size_t)1024 * KDIM;
        float c[2][4][4] = {};

        const uint32_t a_lm = (uint32_t)(((wm * 32 + (lane & 15)) * 40 + (lane >> 4) * 8) * 2);
        const uint32_t b_lm = (uint32_t)(FWA_BYTES + (((lane & 15)) * 136 + wn * 32 + (lane >> 4) * 8) * 2);

        #pragma unroll 1
        for (int it = 0; it < NITER; ++it) {
            const int k0 = it * BK;
            // load A (w_proj) 2 float4
            const float* ap = w_proj + (size_t)(m0 + a_row) * KDIM + k0 + a_ks;
            float4 av0 = *reinterpret_cast<const float4*>(ap);
            float4 av1 = *reinterpret_cast<const float4*>(ap + 4);
            // load B (Wv) + gamma, 4 float4 each
            float4 bv[4], gv[4];
            const float* bp = wv + (size_t)(k0 + b_kr) * KDIM + n0 + b_cs;
            #pragma unroll
            for (int i = 0; i < 4; i++) {
                bv[i] = *reinterpret_cast<const float4*>(bp + 4 * i);
                gv[i] = *reinterpret_cast<const float4*>(gamma + n0 + b_cs + 4 * i);
            }
            __syncthreads();   // previous iteration's ldmatrix reads complete
            {
                __half2 h[4];
                h[0] = __floats2half2_rn(av0.x, av0.y);
                h[1] = __floats2half2_rn(av0.z, av0.w);
                h[2] = __floats2half2_rn(av1.x, av1.y);
                h[3] = __floats2half2_rn(av1.z, av1.w);
                sts16_h8(sbase + (uint32_t)(a_row * 80 + a_ks * 2), h);
                #pragma unroll
                for (int i = 0; i < 2; i++) {
                    #pragma unroll
                    for (int j = 0; j < 2; j++) {
                        float4 v = bv[i * 2 + j], g = gv[i * 2 + j];
                        h[j * 2 + 0] = __floats2half2_rn(v.x * g.x, v.y * g.y);
                        h[j * 2 + 1] = __floats2half2_rn(v.z * g.z, v.w * g.w);
                    }
                    sts16_h8(sbase + (uint32_t)(FWA_BYTES + b_kr * 272 + b_cs * 2 + i * 16), h);
                }
            }
            __syncthreads();

            #pragma unroll
            for (int kk = 0; kk < 2; kk++) {
                uint32_t a[2][4];
                #pragma unroll
                for (int mt = 0; mt < 2; mt++)
                    LDSM_X4(a[mt][0], a[mt][1], a[mt][2], a[mt][3],
                            sbase + a_lm + mt * (16 * 80) + kk * 32);
                uint32_t b[4][2];
                #pragma unroll
                for (int ntp = 0; ntp < 2; ntp++)
                    LDSM_X4_T(b[ntp * 2][0], b[ntp * 2][1], b[ntp * 2 + 1][0], b[ntp * 2 + 1][1],
                              sbase + b_lm + kk * (16 * 272) + ntp * 32);
                #pragma unroll
                for (int mt = 0; mt < 2; mt++)
                    #pragma unroll
                    for (int nt = 0; nt < 4; nt++)
                        mma_f16(c[mt][nt], a[mt][0], a[mt][1], a[mt][2], a[mt][3],
                                b[nt][0], b[nt][1]);
            }
        }

        #pragma unroll
        for (int mt = 0; mt < 2; mt++)
            #pragma unroll
            for (int h = 0; h < 2; h++) {
                const int m = m0 + wm * 32 + mt * 16 + ty + h * 8;
                #pragma unroll
                for (int nt = 0; nt < 4; nt++) {
                    const int nc = wn * 32 + nt * 8 + 2 * tx;
                    *reinterpret_cast<__half2*>(Wf + (size_t)m * KDIM + n0 + nc) =
                        __floats2half2_rn(c[mt][nt][h * 2 + 0], c[mt][nt][h * 2 + 1]);
                }
            }
        return;
    }

    if (bx < 96) {
        // ---- fused bias: warp per output row ----
        const int lane = tid & 31;
        const int o    = (bx - 32) * 8 + (tid >> 5);
        const float* wp = w_proj + (size_t)o * KDIM;
        const float* bq = b_qkv + 1024;
        float acc = 0.f;
        #pragma unroll
        for (int i = 0; i < 16; i++) {
            const int k = lane + 32 * i;
            acc = fmaf(wp[k], bq[k], acc);
        }
        #pragma unroll
        for (int off = 16; off > 0; off >>= 1)
            acc += __shfl_xor_sync(0xFFFFFFFFu, acc, off);
        if (lane == 0) bias[o] = acc + b_proj[o];
        return;
    }

    // ---- RMS scale + fp16 convert: 64 tokens/block, 32 pairs x 8 k-groups ----
    {
        float2* red = reinterpret_cast<float2*>(smem);
        const int nb   = bx - 96;
        const int pair = tid & 31;
        const int kg   = tid >> 5;
        const int n    = nb * 64 + pair * 2;

        const float2* p = reinterpret_cast<const float2*>(x + (size_t)(kg * 64) * NDIM + n);
        __half2* ph = reinterpret_cast<__half2*>(xh + (size_t)(kg * 64) * NDIM + n);
        float ax = 0.f, ay = 0.f;
        #pragma unroll 8
        for (int c = 0; c < 64; c++) {
            float2 v = p[(size_t)c * (NDIM / 2)];
            ax = fmaf(v.x, v.x, ax);
            ay = fmaf(v.y, v.y, ay);
            ph[(size_t)c * (NDIM / 2)] = __floats2half2_rn(v.x, v.y);
        }
        red[tid] = make_float2(ax, ay);
        __syncthreads();
        if (tid < 32) {
            float sx = 0.f, sy = 0.f;
            #pragma unroll
            for (int j = 0; j < 8; j++) {
                float2 v = red[tid + 32 * j];
                sx += v.x; sy += v.y;
            }
            float2 sv;
            sv.x = SQRT_C / fmaxf(sqrtf(sx), 1e-12f);
            sv.y = SQRT_C / fmaxf(sqrtf(sy), 1e-12f);
            *reinterpret_cast<float2*>(s + nb * 64 + tid * 2) = sv;
        }
    }
}

// ================= kernel 2: main GEMM (R7-proven, byte-identical) =================
__global__ __launch_bounds__(256, 2) void main_gemm_kernel(
    const __half* __restrict__ A,    // Wf [512,512] fp16
    const __half* __restrict__ Bh,   // x_h [512,32768] fp16 (operand + residual)
    const float* __restrict__ s,
    const float* __restrict__ bias,
    float* __restrict__ C)
{
    extern __shared__ char smem[];
    const uint32_t sbase = smem_u32(smem);
    const int tid  = threadIdx.x;
    const int lane = tid & 31;
    const int wid  = tid >> 5;
    const int wm   = wid >> 2;
    const int wn   = wid & 3;
    const int ty   = lane >> 2;
    const int tx   = lane & 3;
    const int m0   = blockIdx.x * BM;   // 4 m-tiles fastest (L2 reuse of xh)
    const int n0   = blockIdx.y * BN;   // 256 n-tiles

    const int a_row = tid >> 1;
    const int a_sp  = (tid & 1) * 2;
    const int b_row = tid >> 3;
    const int b_sp  = (tid & 7) * 2;
    const __half* a_src = A + (size_t)(m0 + a_row) * KDIM + a_sp * 8;
    const __half* b_src = Bh + (size_t)b_row * NDIM + n0 + b_sp * 8;

    float c[4][4][4] = {};

    auto issue = [&](int ck) {
        const uint32_t ab = sbase + (uint32_t)(ck % STAGES) * STAGE_B;
        const uint32_t bb = ab + A_BYTES;
        const int k0 = ck * BK;
        #pragma unroll
        for (int ss = 0; ss < 2; ss++)
            cp_async16(ab + (uint32_t)(a_row * 80 + (a_sp + ss) * 16), a_src + k0 + ss * 8);
        #pragma unroll
        for (int ss = 0; ss < 2; ss++)
            cp_async16(bb + (uint32_t)(b_row * 272 + (b_sp + ss) * 16),
                       b_src + (size_t)k0 * NDIM + ss * 8);
        asm volatile("cp.async.commit_group;" ::: "memory");
    };

    issue(0); issue(1); issue(2); issue(3);

    const uint32_t a_lm = (uint32_t)(((wm * 64 + (lane & 15)) * AROW_H + (lane >> 4) * 8) * 2);
    const uint32_t b_lm = (uint32_t)(A_BYTES + (((lane & 15)) * BROW_H + wn * 32 + (lane >> 4) * 8) * 2);

    #pragma unroll 1
    for (int it = 0; it < NITER; ++it) {
        if (it + 3 < NITER)      asm volatile("cp.async.wait_group 3;" ::: "memory");
        else if (it + 2 < NITER) asm volatile("cp.async.wait_group 2;" ::: "memory");
        else if (it + 1 < NITER) asm volatile("cp.async.wait_group 1;" ::: "memory");
        else                     asm volatile("cp.async.wait_group 0;" ::: "memory");
        __syncthreads();
        if (it + 4 < NITER) issue(it + 4);

        const uint32_t stb = sbase + (uint32_t)(it % STAGES) * STAGE_B;
        #pragma unroll
        for (int kk = 0; kk < 2; kk++) {
            uint32_t a[4][4];
            #pragma unroll
            for (int mt = 0; mt < 4; mt++)
                LDSM_X4(a[mt][0], a[mt][1], a[mt][2], a[mt][3],
                        stb + a_lm + mt * (16 * AROW_H * 2) + kk * 32);
            uint32_t b[4][2];
            #pragma unroll
            for (int ntp = 0; ntp < 2; ntp++)
                LDSM_X4_T(b[ntp * 2][0], b[ntp * 2][1], b[ntp * 2 + 1][0], b[ntp * 2 + 1][1],
                          stb + b_lm + kk * (16 * BROW_H * 2) + ntp * 32);
            #pragma unroll
            for (int mt = 0; mt < 4; mt++)
                #pragma unroll
                for (int nt = 0; nt < 4; nt++)
                    mma_f16(c[mt][nt], a[mt][0], a[mt][1], a[mt][2], a[mt][3],
                            b[nt][0], b[nt][1]);
        }
    }

    // ---- epilogue: out = D*s[n] + bias[m] + xh[m][n] ----
    #pragma unroll
    for (int mt = 0; mt < 4; mt++) {
        #pragma unroll
        for (int h = 0; h < 2; h++) {
            const int m = m0 + wm * 64 + mt * 16 + ty + h * 8;
            const float bm = bias[m];
            const __half2* xrow = reinterpret_cast<const __half2*>(Bh + (size_t)m * NDIM + n0);
            float* crow = C + (size_t)m * NDIM + n0;
            #pragma unroll
            for (int nt = 0; nt < 4; nt++) {
                const int nc = wn * 32 + nt * 8 + 2 * tx;
                float2 xv = __half22float2(xrow[nc >> 1]);
                float2 sv = *reinterpret_cast<const float2*>(s + n0 + nc);
                float2 ov;
                ov.x = fmaf(c[mt][nt][h * 2 + 0], sv.x, bm + xv.x);
                ov.y = fmaf(c[mt][nt][h * 2 + 1], sv.y, bm + xv.y);
                *reinterpret_cast<float2*>(crow + nc) = ov;
            }
        }
    }
}

// ---------------- launcher ----------------
extern "C" void kernel_launch(void* const* d_in, const int* in_sizes, int n_in,
                              void* d_out, int out_size)
{
    const float* x      = (const float*)d_in[0];
    const float* gamma  = (const float*)d_in[1];
    const float* w_qkv  = (const float*)d_in[2];
    const float* b_qkv  = (const float*)d_in[3];
    const float* w_proj = (const float*)d_in[4];
    const float* b_proj = (const float*)d_in[5];
    float* out = (float*)d_out;

    __half *Wf, *xh;
    float *bias, *s;
    cudaGetSymbolAddress((void**)&Wf,   g_Wf);
    cudaGetSymbolAddress((void**)&xh,   g_xh);
    cudaGetSymbolAddress((void**)&bias, g_bias);
    cudaGetSymbolAddress((void**)&s,    g_s);

    cudaFuncSetAttribute(aux_kernel,
                         cudaFuncAttributeMaxDynamicSharedMemorySize, AUX_SMEM);
    cudaFuncSetAttribute(main_gemm_kernel,
                         cudaFuncAttributeMaxDynamicSharedMemorySize, SMEM_TOTAL);

    // aux: fw(32) + bias(64) + scale(512) = 608 blocks, 3 CTAs/SM
    aux_kernel<<<608, 256, AUX_SMEM>>>(x, gamma, w_qkv, b_qkv, w_proj, b_proj,
                                       Wf, bias, s, xh);

    dim3 grid(MDIM / BM, NDIM / BN);   // (4, 256): m fastest
    main_gemm_kernel<<<grid, 256, SMEM_TOTAL>>>(Wf, xh, s, bias, out);
}

// round 15
// speedup vs baseline: 1.1963x; 1.0076x over previous
#include <cuda_runtime.h>
#include <cuda_fp16.h>
#include <cstdint>
#include <math.h>

// Problem constants (B=1, DIM=512, T=8, H=64, W=64)
#define MDIM 512
#define KDIM 512
#define NDIM 32768
#define SQRT_C 22.62741699796952f

// ---------------- GEMM tiling (main + fw), R7-proven ----------------
#define BM 128
#define BN 128
#define BK 32
#define NITER (KDIM / BK)      // 16
#define STAGES 5
#define AROW_H 40              // A padded row (halves) -> 80B
#define BROW_H 136             // B padded row (halves) -> 272B
#define A_BYTES (BM * AROW_H * 2)      // 10240
#define B_BYTES (BK * BROW_H * 2)      // 8704
#define STAGE_B (A_BYTES + B_BYTES)    // 18944
#define SMEM_TOTAL (STAGES * STAGE_B)  // 94720

// ---------------- scratch ----------------
__device__ __half g_Wf[MDIM * KDIM];      // fused weight, fp16
__device__ __half g_xh[KDIM * NDIM];      // x converted to fp16
__device__ __half g_wph[MDIM * KDIM];     // w_proj fp16
__device__ __half g_wvh[MDIM * KDIM];     // (W_v * gamma) fp16
__device__ float  g_bias[MDIM];
__device__ float  g_s[NDIM];

// ---------------- helpers ----------------
__device__ __forceinline__ uint32_t smem_u32(const void* p) {
    uint32_t a;
    asm("{ .reg .u64 t; cvta.to.shared.u64 t, %1; cvt.u32.u64 %0, t; }" : "=r"(a) : "l"(p));
    return a;
}
__device__ __forceinline__ void cp_async16(uint32_t dst, const void* src) {
    asm volatile("cp.async.cg.shared.global [%0], [%1], 16;" :: "r"(dst), "l"(src) : "memory");
}
#define LDSM_X4(r0, r1, r2, r3, addr)                                         \
    asm volatile("ldmatrix.sync.aligned.m8n8.x4.shared.b16 {%0,%1,%2,%3}, [%4];" \
        : "=r"(r0), "=r"(r1), "=r"(r2), "=r"(r3) : "r"(addr))
#define LDSM_X4_T(r0, r1, r2, r3, addr)                                       \
    asm volatile("ldmatrix.sync.aligned.m8n8.x4.trans.shared.b16 {%0,%1,%2,%3}, [%4];" \
        : "=r"(r0), "=r"(r1), "=r"(r2), "=r"(r3) : "r"(addr))

__device__ __forceinline__ void mma_f16(float c[4], uint32_t a0, uint32_t a1, uint32_t a2, uint32_t a3,
                                        uint32_t b0, uint32_t b1) {
    asm volatile(
        "mma.sync.aligned.m16n8k16.row.col.f32.f16.f16.f32 "
        "{%0,%1,%2,%3}, {%4,%5,%6,%7}, {%8,%9}, {%0,%1,%2,%3};"
        : "+f"(c[0]), "+f"(c[1]), "+f"(c[2]), "+f"(c[3])
        : "r"(a0), "r"(a1), "r"(a2), "r"(a3), "r"(b0), "r"(b1));
}

// ================= kernel A (side stream): weight converts + bias =================
// blocks 0..255  : w_proj -> fp16
// blocks 256..511: (W_v * gamma) -> fp16
// blocks 512..575: fused bias (warp per output row)
__global__ __launch_bounds__(256) void prep_kernel(
    const float* __restrict__ w_proj, const float* __restrict__ w_qkv,
    const float* __restrict__ gamma,  const float* __restrict__ b_qkv,
    const float* __restrict__ b_proj,
    __half* __restrict__ wph, __half* __restrict__ wvh, float* __restrict__ bias)
{
    const int bx  = blockIdx.x;
    const int tid = threadIdx.x;
    if (bx < 256) {
        const int i = (bx * 256 + tid) * 4;
        float4 v = *reinterpret_cast<const float4*>(w_proj + i);
        *reinterpret_cast<__half2*>(wph + i)     = __floats2half2_rn(v.x, v.y);
        *reinterpret_cast<__half2*>(wph + i + 2) = __floats2half2_rn(v.z, v.w);
    } else if (bx < 512) {
        const float* in = w_qkv + (size_t)1024 * KDIM;
        const int i = ((bx - 256) * 256 + tid) * 4;
        const int c = i & (KDIM - 1);
        float4 g = *reinterpret_cast<const float4*>(gamma + c);
        float4 v = *reinterpret_cast<const float4*>(in + i);
        *reinterpret_cast<__half2*>(wvh + i)     = __floats2half2_rn(v.x * g.x, v.y * g.y);
        *reinterpret_cast<__half2*>(wvh + i + 2) = __floats2half2_rn(v.z * g.z, v.w * g.w);
    } else {
        const int lane = tid & 31;
        const int o    = (bx - 512) * 8 + (tid >> 5);
        const float* wp = w_proj + (size_t)o * KDIM;
        const float* bq = b_qkv + 1024;
        float acc = 0.f;
        #pragma unroll
        for (int i = 0; i < 16; i++) {
            const int k = lane + 32 * i;
            acc = fmaf(wp[k], bq[k], acc);
        }
        #pragma unroll
        for (int off = 16; off > 0; off >>= 1)
            acc += __shfl_xor_sync(0xFFFFFFFFu, acc, off);
        if (lane == 0) bias[o] = acc + b_proj[o];
    }
}

// ================= kernel B (main stream): RMS scale + fp16 convert of x =================
// 512 blocks x 64 tokens; 32 regs -> high occupancy, DRAM-bound.
__global__ __launch_bounds__(256) void scale_kernel(
    const float* __restrict__ x, float* __restrict__ s, __half* __restrict__ xh)
{
    __shared__ float2 red[256];
    const int tid  = threadIdx.x;
    const int pair = tid & 31;
    const int kg   = tid >> 5;          // 0..7, 64 k each
    const int n    = blockIdx.x * 64 + pair * 2;

    const float2* p = reinterpret_cast<const float2*>(x + (size_t)(kg * 64) * NDIM + n);
    __half2* ph = reinterpret_cast<__half2*>(xh + (size_t)(kg * 64) * NDIM + n);
    float ax = 0.f, ay = 0.f;
    #pragma unroll 8
    for (int c = 0; c < 64; c++) {
        float2 v = p[(size_t)c * (NDIM / 2)];
        ax = fmaf(v.x, v.x, ax);
        ay = fmaf(v.y, v.y, ay);
        ph[(size_t)c * (NDIM / 2)] = __floats2half2_rn(v.x, v.y);
    }
    red[tid] = make_float2(ax, ay);
    __syncthreads();
    if (tid < 32) {
        float sx = 0.f, sy = 0.f;
        #pragma unroll
        for (int j = 0; j < 8; j++) {
            float2 v = red[tid + 32 * j];
            sx += v.x; sy += v.y;
        }
        float2 sv;
        sv.x = SQRT_C / fmaxf(sqrtf(sx), 1e-12f);
        sv.y = SQRT_C / fmaxf(sqrtf(sy), 1e-12f);
        *reinterpret_cast<float2*>(s + blockIdx.x * 64 + tid * 2) = sv;
    }
}

// ================= kernel C (side stream): fuse-weights GEMM (16 blocks) =================
__global__ __launch_bounds__(256, 2) void fw_kernel(
    const __half* __restrict__ Awp, const __half* __restrict__ Bwv,
    __half* __restrict__ Wf)
{
    extern __shared__ char smem[];
    const uint32_t sbase = smem_u32(smem);
    const int tid  = threadIdx.x;
    const int lane = tid & 31;
    const int wid  = tid >> 5;
    const int wm   = wid >> 2;
    const int wn   = wid & 3;
    const int ty   = lane >> 2;
    const int tx   = lane & 3;
    const int m0   = (blockIdx.x >> 2) * BM;
    const int n0   = (blockIdx.x & 3) * BN;

    const int a_row = tid >> 1;
    const int a_sp  = (tid & 1) * 2;
    const int b_row = tid >> 3;
    const int b_sp  = (tid & 7) * 2;
    const __half* a_src = Awp + (size_t)(m0 + a_row) * KDIM + a_sp * 8;
    const __half* b_src = Bwv + (size_t)b_row * 512 + n0 + b_sp * 8;

    float c[4][4][4] = {};

    auto issue = [&](int ck) {
        const uint32_t ab = sbase + (uint32_t)(ck % STAGES) * STAGE_B;
        const uint32_t bb = ab + A_BYTES;
        const int k0 = ck * BK;
        #pragma unroll
        for (int ss = 0; ss < 2; ss++)
            cp_async16(ab + (uint32_t)(a_row * 80 + (a_sp + ss) * 16), a_src + k0 + ss * 8);
        #pragma unroll
        for (int ss = 0; ss < 2; ss++)
            cp_async16(bb + (uint32_t)(b_row * 272 + (b_sp + ss) * 16),
                       b_src + (size_t)k0 * 512 + ss * 8);
        asm volatile("cp.async.commit_group;" ::: "memory");
    };

    issue(0); issue(1); issue(2); issue(3);

    const uint32_t a_lm = (uint32_t)(((wm * 64 + (lane & 15)) * AROW_H + (lane >> 4) * 8) * 2);
    const uint32_t b_lm = (uint32_t)(A_BYTES + (((lane & 15)) * BROW_H + wn * 32 + (lane >> 4) * 8) * 2);

    #pragma unroll 1
    for (int it = 0; it < NITER; ++it) {
        if (it + 3 < NITER)      asm volatile("cp.async.wait_group 3;" ::: "memory");
        else if (it + 2 < NITER) asm volatile("cp.async.wait_group 2;" ::: "memory");
        else if (it + 1 < NITER) asm volatile("cp.async.wait_group 1;" ::: "memory");
        else                     asm volatile("cp.async.wait_group 0;" ::: "memory");
        __syncthreads();
        if (it + 4 < NITER) issue(it + 4);

        const uint32_t stb = sbase + (uint32_t)(it % STAGES) * STAGE_B;
        #pragma unroll
        for (int kk = 0; kk < 2; kk++) {
            uint32_t a[4][4];
            #pragma unroll
            for (int mt = 0; mt < 4; mt++)
                LDSM_X4(a[mt][0], a[mt][1], a[mt][2], a[mt][3],
                        stb + a_lm + mt * (16 * AROW_H * 2) + kk * 32);
            uint32_t b[4][2];
            #pragma unroll
            for (int ntp = 0; ntp < 2; ntp++)
                LDSM_X4_T(b[ntp * 2][0], b[ntp * 2][1], b[ntp * 2 + 1][0], b[ntp * 2 + 1][1],
                          stb + b_lm + kk * (16 * BROW_H * 2) + ntp * 32);
            #pragma unroll
            for (int mt = 0; mt < 4; mt++)
                #pragma unroll
                for (int nt = 0; nt < 4; nt++)
                    mma_f16(c[mt][nt], a[mt][0], a[mt][1], a[mt][2], a[mt][3],
                            b[nt][0], b[nt][1]);
        }
    }

    #pragma unroll
    for (int mt = 0; mt < 4; mt++)
        #pragma unroll
        for (int h = 0; h < 2; h++) {
            const int m = m0 + wm * 64 + mt * 16 + ty + h * 8;
            #pragma unroll
            for (int nt = 0; nt < 4; nt++) {
                const int nc = wn * 32 + nt * 8 + 2 * tx;
                *reinterpret_cast<__half2*>(Wf + (size_t)m * KDIM + n0 + nc) =
                    __floats2half2_rn(c[mt][nt][h * 2 + 0], c[mt][nt][h * 2 + 1]);
            }
        }
}

// ================= kernel D: main GEMM (R7-proven, byte-identical) =================
__global__ __launch_bounds__(256, 2) void main_gemm_kernel(
    const __half* __restrict__ A,    // Wf [512,512] fp16
    const __half* __restrict__ Bh,   // x_h [512,32768] fp16 (operand + residual)
    const float* __restrict__ s,
    const float* __restrict__ bias,
    float* __restrict__ C)
{
    extern __shared__ char smem[];
    const uint32_t sbase = smem_u32(smem);
    const int tid  = threadIdx.x;
    const int lane = tid & 31;
    const int wid  = tid >> 5;
    const int wm   = wid >> 2;
    const int wn   = wid & 3;
    const int ty   = lane >> 2;
    const int tx   = lane & 3;
    const int m0   = blockIdx.x * BM;   // 4 m-tiles fastest (L2 reuse of xh)
    const int n0   = blockIdx.y * BN;   // 256 n-tiles

    const int a_row = tid >> 1;
    const int a_sp  = (tid & 1) * 2;
    const int b_row = tid >> 3;
    const int b_sp  = (tid & 7) * 2;
    const __half* a_src = A + (size_t)(m0 + a_row) * KDIM + a_sp * 8;
    const __half* b_src = Bh + (size_t)b_row * NDIM + n0 + b_sp * 8;

    float c[4][4][4] = {};

    auto issue = [&](int ck) {
        const uint32_t ab = sbase + (uint32_t)(ck % STAGES) * STAGE_B;
        const uint32_t bb = ab + A_BYTES;
        const int k0 = ck * BK;
        #pragma unroll
        for (int ss = 0; ss < 2; ss++)
            cp_async16(ab + (uint32_t)(a_row * 80 + (a_sp + ss) * 16), a_src + k0 + ss * 8);
        #pragma unroll
        for (int ss = 0; ss < 2; ss++)
            cp_async16(bb + (uint32_t)(b_row * 272 + (b_sp + ss) * 16),
                       b_src + (size_t)k0 * NDIM + ss * 8);
        asm volatile("cp.async.commit_group;" ::: "memory");
    };

    issue(0); issue(1); issue(2); issue(3);

    const uint32_t a_lm = (uint32_t)(((wm * 64 + (lane & 15)) * AROW_H + (lane >> 4) * 8) * 2);
    const uint32_t b_lm = (uint32_t)(A_BYTES + (((lane & 15)) * BROW_H + wn * 32 + (lane >> 4) * 8) * 2);

    #pragma unroll 1
    for (int it = 0; it < NITER; ++it) {
        if (it + 3 < NITER)      asm volatile("cp.async.wait_group 3;" ::: "memory");
        else if (it + 2 < NITER) asm volatile("cp.async.wait_group 2;" ::: "memory");
        else if (it + 1 < NITER) asm volatile("cp.async.wait_group 1;" ::: "memory");
        else                     asm volatile("cp.async.wait_group 0;" ::: "memory");
        __syncthreads();
        if (it + 4 < NITER) issue(it + 4);

        const uint32_t stb = sbase + (uint32_t)(it % STAGES) * STAGE_B;
        #pragma unroll
        for (int kk = 0; kk < 2; kk++) {
            uint32_t a[4][4];
            #pragma unroll
            for (int mt = 0; mt < 4; mt++)
                LDSM_X4(a[mt][0], a[mt][1], a[mt][2], a[mt][3],
                        stb + a_lm + mt * (16 * AROW_H * 2) + kk * 32);
            uint32_t b[4][2];
            #pragma unroll
            for (int ntp = 0; ntp < 2; ntp++)
                LDSM_X4_T(b[ntp * 2][0], b[ntp * 2][1], b[ntp * 2 + 1][0], b[ntp * 2 + 1][1],
                          stb + b_lm + kk * (16 * BROW_H * 2) + ntp * 32);
            #pragma unroll
            for (int mt = 0; mt < 4; mt++)
                #pragma unroll
                for (int nt = 0; nt < 4; nt++)
                    mma_f16(c[mt][nt], a[mt][0], a[mt][1], a[mt][2], a[mt][3],
                            b[nt][0], b[nt][1]);
        }
    }

    // ---- epilogue: out = D*s[n] + bias[m] + xh[m][n] ----
    #pragma unroll
    for (int mt = 0; mt < 4; mt++) {
        #pragma unroll
        for (int h = 0; h < 2; h++) {
            const int m = m0 + wm * 64 + mt * 16 + ty + h * 8;
            const float bm = bias[m];
            const __half2* xrow = reinterpret_cast<const __half2*>(Bh + (size_t)m * NDIM + n0);
            float* crow = C + (size_t)m * NDIM + n0;
            #pragma unroll
            for (int nt = 0; nt < 4; nt++) {
                const int nc = wn * 32 + nt * 8 + 2 * tx;
                float2 xv = __half22float2(xrow[nc >> 1]);
                float2 sv = *reinterpret_cast<const float2*>(s + n0 + nc);
                float2 ov;
                ov.x = fmaf(c[mt][nt][h * 2 + 0], sv.x, bm + xv.x);
                ov.y = fmaf(c[mt][nt][h * 2 + 1], sv.y, bm + xv.y);
                *reinterpret_cast<float2*>(crow + nc) = ov;
            }
        }
    }
}

// ---------------- launcher: fork-join two-stream graph ----------------
extern "C" void kernel_launch(void* const* d_in, const int* in_sizes, int n_in,
                              void* d_out, int out_size)
{
    const float* x      = (const float*)d_in[0];
    const float* gamma  = (const float*)d_in[1];
    const float* w_qkv  = (const float*)d_in[2];
    const float* b_qkv  = (const float*)d_in[3];
    const float* w_proj = (const float*)d_in[4];
    const float* b_proj = (const float*)d_in[5];
    float* out = (float*)d_out;

    __half *Wf, *xh, *wph, *wvh;
    float *bias, *s;
    cudaGetSymbolAddress((void**)&Wf,   g_Wf);
    cudaGetSymbolAddress((void**)&xh,   g_xh);
    cudaGetSymbolAddress((void**)&wph,  g_wph);
    cudaGetSymbolAddress((void**)&wvh,  g_wvh);
    cudaGetSymbolAddress((void**)&bias, g_bias);
    cudaGetSymbolAddress((void**)&s,    g_s);

    // One-time resource init (first call happens during the un-captured
    // correctness run; the captured work is identical on every call).
    static cudaStream_t s2 = nullptr;
    static cudaEvent_t evFork = nullptr, evJoin = nullptr;
    static bool attrs_set = false;
    if (!attrs_set) {
        cudaStreamCreateWithFlags(&s2, cudaStreamNonBlocking);
        cudaEventCreateWithFlags(&evFork, cudaEventDisableTiming);
        cudaEventCreateWithFlags(&evJoin, cudaEventDisableTiming);
        cudaFuncSetAttribute(fw_kernel,
                             cudaFuncAttributeMaxDynamicSharedMemorySize, SMEM_TOTAL);
        cudaFuncSetAttribute(main_gemm_kernel,
                             cudaFuncAttributeMaxDynamicSharedMemorySize, SMEM_TOTAL);
        attrs_set = true;
    }

    // fork: side stream does converts+bias then fw-GEMM
    cudaEventRecord(evFork, 0);
    cudaStreamWaitEvent(s2, evFork, 0);
    prep_kernel<<<576, 256, 0, s2>>>(w_proj, w_qkv, gamma, b_qkv, b_proj, wph, wvh, bias);
    fw_kernel<<<16, 256, SMEM_TOTAL, s2>>>(wph, wvh, Wf);
    cudaEventRecord(evJoin, s2);

    // main stream: scale (concurrent with side stream)
    scale_kernel<<<512, 256>>>(x, s, xh);

    // join, then main GEMM
    cudaStreamWaitEvent(0, evJoin, 0);
    dim3 grid(MDIM / BM, NDIM / BN);   // (4, 256): m fastest
    main_gemm_kernel<<<grid, 256, SMEM_TOTAL>>>(Wf, xh, s, bias, out);
}

// round 16
// speedup vs baseline: 1.2161x; 1.0165x over previous
#include <cuda_runtime.h>
#include <cuda_fp16.h>
#include <cstdint>
#include <math.h>

// Problem constants (B=1, DIM=512, T=8, H=64, W=64)
#define MDIM 512
#define KDIM 512
#define NDIM 32768
#define SQRT_C 22.62741699796952f

// ---------------- main GEMM tiling (R7-proven) ----------------
#define BM 128
#define BN 128
#define BK 32
#define NITER (KDIM / BK)      // 16
#define STAGES 5
#define AROW_H 40              // A padded row (halves) -> 80B
#define BROW_H 136             // B padded row (halves) -> 272B
#define A_BYTES (BM * AROW_H * 2)      // 10240
#define B_BYTES (BK * BROW_H * 2)      // 8704
#define STAGE_B (A_BYTES + B_BYTES)    // 18944
#define SMEM_TOTAL (STAGES * STAGE_B)  // 94720

// ---------------- fw GEMM tiling: 64x64 tiles, 64 CTAs ----------------
#define FWA_BYTES (64 * 80)            // 5120  (64 rows x 80B)
#define FWB_BYTES (32 * 144)           // 4608  (32 k-rows x 144B, conflict-free)
#define FW_STAGE (FWA_BYTES + FWB_BYTES)   // 9728
#define FW_SMEM (STAGES * FW_STAGE)        // 48640

// ---------------- scratch ----------------
__device__ __half g_Wf[MDIM * KDIM];      // fused weight, fp16
__device__ __half g_xh[KDIM * NDIM];      // x converted to fp16
__device__ __half g_wph[MDIM * KDIM];     // w_proj fp16
__device__ __half g_wvh[MDIM * KDIM];     // (W_v * gamma) fp16
__device__ float  g_bias[MDIM];
__device__ float  g_s[NDIM];

// ---------------- helpers ----------------
__device__ __forceinline__ uint32_t smem_u32(const void* p) {
    uint32_t a;
    asm("{ .reg .u64 t; cvta.to.shared.u64 t, %1; cvt.u32.u64 %0, t; }" : "=r"(a) : "l"(p));
    return a;
}
__device__ __forceinline__ void cp_async16(uint32_t dst, const void* src) {
    asm volatile("cp.async.cg.shared.global [%0], [%1], 16;" :: "r"(dst), "l"(src) : "memory");
}
#define LDSM_X4(r0, r1, r2, r3, addr)                                         \
    asm volatile("ldmatrix.sync.aligned.m8n8.x4.shared.b16 {%0,%1,%2,%3}, [%4];" \
        : "=r"(r0), "=r"(r1), "=r"(r2), "=r"(r3) : "r"(addr))
#define LDSM_X4_T(r0, r1, r2, r3, addr)                                       \
    asm volatile("ldmatrix.sync.aligned.m8n8.x4.trans.shared.b16 {%0,%1,%2,%3}, [%4];" \
        : "=r"(r0), "=r"(r1), "=r"(r2), "=r"(r3) : "r"(addr))

__device__ __forceinline__ void mma_f16(float c[4], uint32_t a0, uint32_t a1, uint32_t a2, uint32_t a3,
                                        uint32_t b0, uint32_t b1) {
    asm volatile(
        "mma.sync.aligned.m16n8k16.row.col.f32.f16.f16.f32 "
        "{%0,%1,%2,%3}, {%4,%5,%6,%7}, {%8,%9}, {%0,%1,%2,%3};"
        : "+f"(c[0]), "+f"(c[1]), "+f"(c[2]), "+f"(c[3])
        : "r"(a0), "r"(a1), "r"(a2), "r"(a3), "r"(b0), "r"(b1));
}

// ================= kernel 1: all streaming prep, one launch, high occupancy =================
// blocks 0..1023   : RMS scale + fp16 conversion of x (32 tokens/block)
// blocks 1024..1279: w_proj -> fp16
// blocks 1280..1535: (W_v * gamma) -> fp16
// blocks 1536..1599: fused bias (warp per output row)
__global__ __launch_bounds__(256) void stream_prep_kernel(
    const float* __restrict__ x,
    const float* __restrict__ gamma,
    const float* __restrict__ w_qkv,
    const float* __restrict__ b_qkv,
    const float* __restrict__ w_proj,
    const float* __restrict__ b_proj,
    __half* __restrict__ wph, __half* __restrict__ wvh,
    float* __restrict__ bias,
    float* __restrict__ s, __half* __restrict__ xh)
{
    __shared__ float2 red[256];
    const int bx  = blockIdx.x;
    const int tid = threadIdx.x;

    if (bx < 1024) {
        // ---- RMS scale + fp16 convert: 32 tokens, 16 pairs x 16 k-groups ----
        const int pair = tid & 15;          // token pair 0..15
        const int kg   = tid >> 4;          // k-group 0..15, 32 k each
        const int n    = bx * 32 + pair * 2;

        const float2* p = reinterpret_cast<const float2*>(x + (size_t)(kg * 32) * NDIM + n);
        __half2* ph = reinterpret_cast<__half2*>(xh + (size_t)(kg * 32) * NDIM + n);
        float ax = 0.f, ay = 0.f;
        #pragma unroll 8
        for (int c = 0; c < 32; c++) {
            float2 v = p[(size_t)c * (NDIM / 2)];
            ax = fmaf(v.x, v.x, ax);
            ay = fmaf(v.y, v.y, ay);
            ph[(size_t)c * (NDIM / 2)] = __floats2half2_rn(v.x, v.y);
        }
        red[tid] = make_float2(ax, ay);
        __syncthreads();
        if (tid < 16) {
            float sx = 0.f, sy = 0.f;
            #pragma unroll
            for (int j = 0; j < 16; j++) {
                float2 v = red[tid + 16 * j];
                sx += v.x; sy += v.y;
            }
            float2 sv;
            sv.x = SQRT_C / fmaxf(sqrtf(sx), 1e-12f);
            sv.y = SQRT_C / fmaxf(sqrtf(sy), 1e-12f);
            *reinterpret_cast<float2*>(s + bx * 32 + tid * 2) = sv;
        }
        return;
    }

    if (bx < 1280) {
        const int i = ((bx - 1024) * 256 + tid) * 4;
        float4 v = *reinterpret_cast<const float4*>(w_proj + i);
        *reinterpret_cast<__half2*>(wph + i)     = __floats2half2_rn(v.x, v.y);
        *reinterpret_cast<__half2*>(wph + i + 2) = __floats2half2_rn(v.z, v.w);
        return;
    }

    if (bx < 1536) {
        const float* in = w_qkv + (size_t)1024 * KDIM;
        const int i = ((bx - 1280) * 256 + tid) * 4;
        const int c = i & (KDIM - 1);
        float4 g = *reinterpret_cast<const float4*>(gamma + c);
        float4 v = *reinterpret_cast<const float4*>(in + i);
        *reinterpret_cast<__half2*>(wvh + i)     = __floats2half2_rn(v.x * g.x, v.y * g.y);
        *reinterpret_cast<__half2*>(wvh + i + 2) = __floats2half2_rn(v.z * g.z, v.w * g.w);
        return;
    }

    // ---- fused bias: warp per output row ----
    {
        const int lane = tid & 31;
        const int o    = (bx - 1536) * 8 + (tid >> 5);
        const float* wp = w_proj + (size_t)o * KDIM;
        const float* bq = b_qkv + 1024;
        float acc = 0.f;
        #pragma unroll
        for (int i = 0; i < 16; i++) {
            const int k = lane + 32 * i;
            acc = fmaf(wp[k], bq[k], acc);
        }
        #pragma unroll
        for (int off = 16; off > 0; off >>= 1)
            acc += __shfl_xor_sync(0xFFFFFFFFu, acc, off);
        if (lane == 0) bias[o] = acc + b_proj[o];
    }
}

// ================= kernel 2: fuse-weights GEMM, 64x64 tiles (64 CTAs) =================
// Wf = wph @ wvh. 8 warps = 2m x 4n, warp tile 32x16.
__global__ __launch_bounds__(256, 2) void fw_kernel(
    const __half* __restrict__ Awp, const __half* __restrict__ Bwv,
    __half* __restrict__ Wf)
{
    extern __shared__ char smem[];
    const uint32_t sbase = smem_u32(smem);
    const int tid  = threadIdx.x;
    const int lane = tid & 31;
    const int wid  = tid >> 5;
    const int wm   = wid >> 2;          // 0..1 (32-row halves)
    const int wn   = wid & 3;           // 0..3 (16-col groups)
    const int ty   = lane >> 2;
    const int tx   = lane & 3;
    const int m0   = (blockIdx.x >> 3) * 64;
    const int n0   = (blockIdx.x & 7) * 64;

    // loaders: A 64 rows x 64B (4 segs) = 256 segs; B 32 rows x 128B (8 segs) = 256 segs
    const int a_row = tid >> 2;
    const int a_seg = tid & 3;
    const int b_row = tid >> 3;
    const int b_seg = tid & 7;
    const __half* a_src = Awp + (size_t)(m0 + a_row) * KDIM + a_seg * 8;
    const __half* b_src = Bwv + (size_t)b_row * 512 + n0 + b_seg * 8;

    float c[2][2][4] = {};

    auto issue = [&](int ck) {
        const uint32_t ab = sbase + (uint32_t)(ck % STAGES) * FW_STAGE;
        const uint32_t bb = ab + FWA_BYTES;
        const int k0 = ck * BK;
        cp_async16(ab + (uint32_t)(a_row * 80 + a_seg * 16), a_src + k0);
        cp_async16(bb + (uint32_t)(b_row * 144 + b_seg * 16), b_src + (size_t)k0 * 512);
        asm volatile("cp.async.commit_group;" ::: "memory");
    };

    issue(0); issue(1); issue(2); issue(3);

    const uint32_t a_lm = (uint32_t)(((wm * 32 + (lane & 15)) * 40 + (lane >> 4) * 8) * 2);
    const uint32_t b_lm = (uint32_t)(FWA_BYTES + ((lane & 15) * 144 + wn * 32 + (lane >> 4) * 16));

    #pragma unroll 1
    for (int it = 0; it < NITER; ++it) {
        if (it + 3 < NITER)      asm volatile("cp.async.wait_group 3;" ::: "memory");
        else if (it + 2 < NITER) asm volatile("cp.async.wait_group 2;" ::: "memory");
        else if (it + 1 < NITER) asm volatile("cp.async.wait_group 1;" ::: "memory");
        else                     asm volatile("cp.async.wait_group 0;" ::: "memory");
        __syncthreads();
        if (it + 4 < NITER) issue(it + 4);

        const uint32_t stb = sbase + (uint32_t)(it % STAGES) * FW_STAGE;
        #pragma unroll
        for (int kk = 0; kk < 2; kk++) {
            uint32_t a[2][4];
            #pragma unroll
            for (int mt = 0; mt < 2; mt++)
                LDSM_X4(a[mt][0], a[mt][1], a[mt][2], a[mt][3],
                        stb + a_lm + mt * (16 * 80) + kk * 32);
            uint32_t b[2][2];
            LDSM_X4_T(b[0][0], b[0][1], b[1][0], b[1][1],
                      stb + b_lm + kk * (16 * 144));
            #pragma unroll
            for (int mt = 0; mt < 2; mt++)
                #pragma unroll
                for (int nt = 0; nt < 2; nt++)
                    mma_f16(c[mt][nt], a[mt][0], a[mt][1], a[mt][2], a[mt][3],
                            b[nt][0], b[nt][1]);
        }
    }

    #pragma unroll
    for (int mt = 0; mt < 2; mt++)
        #pragma unroll
        for (int h = 0; h < 2; h++) {
            const int m = m0 + wm * 32 + mt * 16 + ty + h * 8;
            #pragma unroll
            for (int nt = 0; nt < 2; nt++) {
                const int nc = wn * 16 + nt * 8 + 2 * tx;
                *reinterpret_cast<__half2*>(Wf + (size_t)m * KDIM + n0 + nc) =
                    __floats2half2_rn(c[mt][nt][h * 2 + 0], c[mt][nt][h * 2 + 1]);
            }
        }
}

// ================= kernel 3: main GEMM (R7-proven, byte-identical) =================
__global__ __launch_bounds__(256, 2) void main_gemm_kernel(
    const __half* __restrict__ A,    // Wf [512,512] fp16
    const __half* __restrict__ Bh,   // x_h [512,32768] fp16 (operand + residual)
    const float* __restrict__ s,
    const float* __restrict__ bias,
    float* __restrict__ C)
{
    extern __shared__ char smem[];
    const uint32_t sbase = smem_u32(smem);
    const int tid  = threadIdx.x;
    const int lane = tid & 31;
    const int wid  = tid >> 5;
    const int wm   = wid >> 2;
    const int wn   = wid & 3;
    const int ty   = lane >> 2;
    const int tx   = lane & 3;
    const int m0   = blockIdx.x * BM;   // 4 m-tiles fastest (L2 reuse of xh)
    const int n0   = blockIdx.y * BN;   // 256 n-tiles

    const int a_row = tid >> 1;
    const int a_sp  = (tid & 1) * 2;
    const int b_row = tid >> 3;
    const int b_sp  = (tid & 7) * 2;
    const __half* a_src = A + (size_t)(m0 + a_row) * KDIM + a_sp * 8;
    const __half* b_src = Bh + (size_t)b_row * NDIM + n0 + b_sp * 8;

    float c[4][4][4] = {};

    auto issue = [&](int ck) {
        const uint32_t ab = sbase + (uint32_t)(ck % STAGES) * STAGE_B;
        const uint32_t bb = ab + A_BYTES;
        const int k0 = ck * BK;
        #pragma unroll
        for (int ss = 0; ss < 2; ss++)
            cp_async16(ab + (uint32_t)(a_row * 80 + (a_sp + ss) * 16), a_src + k0 + ss * 8);
        #pragma unroll
        for (int ss = 0; ss < 2; ss++)
            cp_async16(bb + (uint32_t)(b_row * 272 + (b_sp + ss) * 16),
                       b_src + (size_t)k0 * NDIM + ss * 8);
        asm volatile("cp.async.commit_group;" ::: "memory");
    };

    issue(0); issue(1); issue(2); issue(3);

    const uint32_t a_lm = (uint32_t)(((wm * 64 + (lane & 15)) * AROW_H + (lane >> 4) * 8) * 2);
    const uint32_t b_lm = (uint32_t)(A_BYTES + (((lane & 15)) * BROW_H + wn * 32 + (lane >> 4) * 8) * 2);

    #pragma unroll 1
    for (int it = 0; it < NITER; ++it) {
        if (it + 3 < NITER)      asm volatile("cp.async.wait_group 3;" ::: "memory");
        else if (it + 2 < NITER) asm volatile("cp.async.wait_group 2;" ::: "memory");
        else if (it + 1 < NITER) asm volatile("cp.async.wait_group 1;" ::: "memory");
        else                     asm volatile("cp.async.wait_group 0;" ::: "memory");
        __syncthreads();
        if (it + 4 < NITER) issue(it + 4);

        const uint32_t stb = sbase + (uint32_t)(it % STAGES) * STAGE_B;
        #pragma unroll
        for (int kk = 0; kk < 2; kk++) {
            uint32_t a[4][4];
            #pragma unroll
            for (int mt = 0; mt < 4; mt++)
                LDSM_X4(a[mt][0], a[mt][1], a[mt][2], a[mt][3],
                        stb + a_lm + mt * (16 * AROW_H * 2) + kk * 32);
            uint32_t b[4][2];
            #pragma unroll
            for (int ntp = 0; ntp < 2; ntp++)
                LDSM_X4_T(b[ntp * 2][0], b[ntp * 2][1], b[ntp * 2 + 1][0], b[ntp * 2 + 1][1],
                          stb + b_lm + kk * (16 * BROW_H * 2) + ntp * 32);
            #pragma unroll
            for (int mt = 0; mt < 4; mt++)
                #pragma unroll
                for (int nt = 0; nt < 4; nt++)
                    mma_f16(c[mt][nt], a[mt][0], a[mt][1], a[mt][2], a[mt][3],
                            b[nt][0], b[nt][1]);
        }
    }

    // ---- epilogue: out = D*s[n] + bias[m] + xh[m][n] ----
    #pragma unroll
    for (int mt = 0; mt < 4; mt++) {
        #pragma unroll
        for (int h = 0; h < 2; h++) {
            const int m = m0 + wm * 64 + mt * 16 + ty + h * 8;
            const float bm = bias[m];
            const __half2* xrow = reinterpret_cast<const __half2*>(Bh + (size_t)m * NDIM + n0);
            float* crow = C + (size_t)m * NDIM + n0;
            #pragma unroll
            for (int nt = 0; nt < 4; nt++) {
                const int nc = wn * 32 + nt * 8 + 2 * tx;
                float2 xv = __half22float2(xrow[nc >> 1]);
                float2 sv = *reinterpret_cast<const float2*>(s + n0 + nc);
                float2 ov;
                ov.x = fmaf(c[mt][nt][h * 2 + 0], sv.x, bm + xv.x);
                ov.y = fmaf(c[mt][nt][h * 2 + 1], sv.y, bm + xv.y);
                *reinterpret_cast<float2*>(crow + nc) = ov;
            }
        }
    }
}

// ---------------- launcher ----------------
extern "C" void kernel_launch(void* const* d_in, const int* in_sizes, int n_in,
                              void* d_out, int out_size)
{
    const float* x      = (const float*)d_in[0];
    const float* gamma  = (const float*)d_in[1];
    const float* w_qkv  = (const float*)d_in[2];
    const float* b_qkv  = (const float*)d_in[3];
    const float* w_proj = (const float*)d_in[4];
    const float* b_proj = (const float*)d_in[5];
    float* out = (float*)d_out;

    __half *Wf, *xh, *wph, *wvh;
    float *bias, *s;
    cudaGetSymbolAddress((void**)&Wf,   g_Wf);
    cudaGetSymbolAddress((void**)&xh,   g_xh);
    cudaGetSymbolAddress((void**)&wph,  g_wph);
    cudaGetSymbolAddress((void**)&wvh,  g_wvh);
    cudaGetSymbolAddress((void**)&bias, g_bias);
    cudaGetSymbolAddress((void**)&s,    g_s);

    cudaFuncSetAttribute(fw_kernel,
                         cudaFuncAttributeMaxDynamicSharedMemorySize, FW_SMEM);
    cudaFuncSetAttribute(main_gemm_kernel,
                         cudaFuncAttributeMaxDynamicSharedMemorySize, SMEM_TOTAL);

    // kernel1: scale(1024) + wconv(512) + bias(64) = 1600 blocks, all 32-reg streaming
    stream_prep_kernel<<<1600, 256>>>(x, gamma, w_qkv, b_qkv, w_proj, b_proj,
                                      wph, wvh, bias, s, xh);
    // kernel2: fuse-weights GEMM, 64 CTAs
    fw_kernel<<<64, 256, FW_SMEM>>>(wph, wvh, Wf);
    // kernel3: main GEMM
    dim3 grid(MDIM / BM, NDIM / BN);   // (4, 256): m fastest
    main_gemm_kernel<<<grid, 256, SMEM_TOTAL>>>(Wf, xh, s, bias, out);
}